// round 12
// baseline (speedup 1.0000x reference)
#include <cuda_runtime.h>
#include <cuda_fp16.h>
#include <math.h>
#include <stdint.h>

// ---------------------------------------------------------------------------
// Shapes: N=100000 nodes, E=300000 edges, V=50000
// Layers: F {196,96,192,384,384} (padded {256,128,192,384,384}),
//         H {192,384,768,768,1152}, O {96,192,384,384,576} (W2 N-pad {128,256,384,384,640})
// GEMM: split-fp16 — A = hi+lo, B = hi+lo; 3 MMAs per k16 (err ~2^-22).
// Edge aggregation: CSR (warp per node), no atomics.
// ---------------------------------------------------------------------------
#define N_NODES 100000
#define MAXE    300000
#define VCAP    65536
#define MAXF    384
#define MAXH    1152
#define MAXO    576
#define MAXOP   640

__device__ float  g_feat[(size_t)N_NODES * MAXF];
__device__ float  g_bc  [(size_t)N_NODES * 2 * MAXH];
__device__ float  g_agg [(size_t)N_NODES * MAXH];
__device__ float  g_out2[(size_t)N_NODES * MAXO];
__device__ float  g_vsum[(size_t)VCAP * (MAXO / 3)];
__device__ double g_stats[2 * MAXO];
__device__ float  g_scale[MAXO];
__device__ float  g_shift[MAXO];
__device__ int    g_deg[N_NODES];
__device__ float  g_invdeg[N_NODES];
__device__ int    g_vcnt[VCAP];
__device__ float  g_vinv[VCAP];
// CSR for edges (dst -> list of src)
__device__ int    g_estart[N_NODES + 1];
__device__ int    g_cursor[N_NODES];
__device__ int    g_csr[MAXE];
__device__ int    g_csum[128];
// fp16 hi/lo weights: W1cat^T [2H x Fpad], W2^T [Opad x H]
__device__ __half g_w1h[(size_t)2 * MAXH * MAXF];
__device__ __half g_w1l[(size_t)2 * MAXH * MAXF];
__device__ __half g_w2h[(size_t)MAXOP * MAXH];
__device__ __half g_w2l[(size_t)MAXOP * MAXH];

// ---------------------------------------------------------------------------
// mma.sync helpers (baseline PTX; harness targets plain sm_103 — no tcgen05)
// ---------------------------------------------------------------------------
__device__ __forceinline__ uint32_t smem_u32(const void* p) {
    uint32_t a;
    asm("{ .reg .u64 t; cvta.to.shared.u64 t, %1; cvt.u32.u64 %0, t; }" : "=r"(a) : "l"(p));
    return a;
}
__device__ __forceinline__ void ldsm_x4(uint32_t* r, uint32_t addr) {
    asm volatile("ldmatrix.sync.aligned.m8n8.x4.shared.b16 {%0,%1,%2,%3}, [%4];"
        : "=r"(r[0]), "=r"(r[1]), "=r"(r[2]), "=r"(r[3]) : "r"(addr));
}
__device__ __forceinline__ void ldsm_x2(uint32_t* r, uint32_t addr) {
    asm volatile("ldmatrix.sync.aligned.m8n8.x2.shared.b16 {%0,%1}, [%2];"
        : "=r"(r[0]), "=r"(r[1]) : "r"(addr));
}
__device__ __forceinline__ void mma_f16(float* d, const uint32_t* a, const uint32_t* b) {
    asm volatile("mma.sync.aligned.m16n8k16.row.col.f32.f16.f16.f32 "
        "{%0,%1,%2,%3}, {%4,%5,%6,%7}, {%8,%9}, {%0,%1,%2,%3};"
        : "+f"(d[0]), "+f"(d[1]), "+f"(d[2]), "+f"(d[3])
        : "r"(a[0]), "r"(a[1]), "r"(a[2]), "r"(a[3]), "r"(b[0]), "r"(b[1]));
}
__device__ __forceinline__ void split_f16(float x, __half& h, __half& l) {
    h = __float2half_rn(x);
    l = __float2half_rn(x - __half2float(h));
}

// ---------------------------------------------------------------------------
// NeRF embedding -> padded stride 256 (cols 196..255 zero)
// ---------------------------------------------------------------------------
__global__ void k_embed(const float* __restrict__ x, float* __restrict__ out, int N) {
    int idx = blockIdx.x * blockDim.x + threadIdx.x;
    if (idx >= N * 256) return;
    int n = idx / 256, j = idx % 256;
    const float* xr = x + (size_t)n * 16;
    float val = 0.0f;
    if (j < 189) {
        int g = j / 63, k = j % 63;
        if (k < 3) val = xr[g * 3 + k];
        else {
            int t = k - 3;
            int d = t / 20, fr = (t % 20) >> 1, s = t & 1;
            float ang = xr[g * 3 + d] * (float)(1 << fr);
            val = s ? cosf(ang) : sinf(ang);
        }
    } else if (j < 196) {
        val = xr[9 + (j - 189)];
    }
    out[(size_t)n * 256 + j] = val;
}

// ---------------------------------------------------------------------------
// Degree / vertex counts / CSR build
// ---------------------------------------------------------------------------
__global__ void k_deg(const int* __restrict__ ei, int* __restrict__ deg, int E) {
    int e = blockIdx.x * blockDim.x + threadIdx.x;
    if (e < E) atomicAdd(&deg[ei[E + e]], 1);
}
__global__ void k_invdeg(const int* __restrict__ deg, float* __restrict__ invdeg, int N) {
    int i = blockIdx.x * blockDim.x + threadIdx.x;
    if (i < N) invdeg[i] = deg[i] > 0 ? 1.0f / (float)deg[i] : 0.0f;
}
__global__ void k_vcnt(const int* __restrict__ faces, int* __restrict__ vcnt, int T3) {
    int i = blockIdx.x * blockDim.x + threadIdx.x;
    if (i < T3) atomicAdd(&vcnt[faces[i]], 1);
}
__global__ void k_vinv(const int* __restrict__ vcnt, float* __restrict__ vinv, int V) {
    int i = blockIdx.x * blockDim.x + threadIdx.x;
    if (i < V) vinv[i] = 1.0f / (float)max(vcnt[i], 1);
}
// chunked exclusive scan of deg -> estart (chunks of 1024)
__global__ void k_chunk_sum(const int* __restrict__ deg, int* __restrict__ csum, int N) {
    __shared__ int sh[256];
    int b = blockIdx.x;
    int s = 0;
    for (int i = threadIdx.x; i < 1024; i += 256) {
        int idx = b * 1024 + i;
        if (idx < N) s += deg[idx];
    }
    sh[threadIdx.x] = s;
    __syncthreads();
    for (int st = 128; st > 0; st >>= 1) {
        if (threadIdx.x < st) sh[threadIdx.x] += sh[threadIdx.x + st];
        __syncthreads();
    }
    if (threadIdx.x == 0) csum[b] = sh[0];
}
__global__ void k_chunk_scan(int* __restrict__ csum, int* __restrict__ estart,
                             int nchunks, int N, int E) {
    if (threadIdx.x == 0 && blockIdx.x == 0) {
        int run = 0;
        for (int i = 0; i < nchunks; i++) { int v = csum[i]; csum[i] = run; run += v; }
        estart[N] = E;
    }
}
__global__ void k_node_start(const int* __restrict__ deg, const int* __restrict__ csum,
                             int* __restrict__ estart, int* __restrict__ cursor, int N) {
    int b = blockIdx.x;
    if (threadIdx.x != 0) return;
    int run = csum[b];
    int end = min((b + 1) * 1024, N);
    for (int i = b * 1024; i < end; i++) {
        estart[i] = run;
        cursor[i] = run;
        run += deg[i];
    }
}
__global__ void k_fill_csr(const int* __restrict__ ei, int* __restrict__ cursor,
                           int* __restrict__ csr, int E) {
    int e = blockIdx.x * blockDim.x + threadIdx.x;
    if (e >= E) return;
    int dst = ei[E + e];
    int p = atomicAdd(&cursor[dst], 1);
    csr[p] = ei[e];
}

// ---------------------------------------------------------------------------
// Weight prep (fp16 hi/lo)
// ---------------------------------------------------------------------------
__global__ void k_prep_w1(const float* __restrict__ w1, __half* __restrict__ bh,
                          __half* __restrict__ bl, int F, int H, int Fpad) {
    int idx = blockIdx.x * blockDim.x + threadIdx.x;
    int total = 2 * H * Fpad;
    if (idx >= total) return;
    int h2 = idx / Fpad, f = idx % Fpad;
    float v = 0.0f;
    if (f < F) {
        if (h2 < H) v = w1[(size_t)f * H + h2] - w1[(size_t)(F + f) * H + h2];
        else        v = w1[(size_t)(F + f) * H + (h2 - H)];
    }
    __half h, l; split_f16(v, h, l);
    bh[idx] = h; bl[idx] = l;
}
__global__ void k_prep_w2(const float* __restrict__ w2, __half* __restrict__ bh,
                          __half* __restrict__ bl, int H, int O, int Opad) {
    int idx = blockIdx.x * blockDim.x + threadIdx.x;
    int total = Opad * H;
    if (idx >= total) return;
    int n = idx / H, k = idx % H;
    float v = (n < O) ? w2[(size_t)k * O + n] : 0.0f;
    __half h, l; split_f16(v, h, l);
    bh[idx] = h; bl[idx] = l;
}

// ---------------------------------------------------------------------------
// Split-fp16 GEMM via mma.sync: C[M,Nc] = diag(rowScale)*A[M,K] @ Bt^T (+gated bias)
// A fp32 [M,lda] (K mult of 32, zero-padded), Bt fp16 hi/lo [Npad,K] K-major,
// Npad mult of 128. Tile 128x128, BK=32, 256 threads (2x4 warps, warp 64x32).
// 3 MMAs per k16: AhBh + AhBl + AlBh.
// ---------------------------------------------------------------------------
#define GM_BM 128
#define GM_BN 128
#define GM_BK 32
// smem: Ah [128][40]half (10240B), Al (10240B), Bh [128][72]half (18432B), Bl (18432B)
#define SM_AH 0
#define SM_AL 10240
#define SM_BH 20480
#define SM_BL 38912
#define GM_SMEM 57344

__global__ __launch_bounds__(256, 1)
void k_gemm_mma(const float* __restrict__ A,
                const __half* __restrict__ Bh, const __half* __restrict__ Bl,
                float* __restrict__ C, int M, int K, int Nc, int lda, int ldc,
                const float* __restrict__ rowScale, const float* __restrict__ bias)
{
    extern __shared__ char sm[];
    const uint32_t sb = smem_u32(sm);
    const int tid = threadIdx.x;
    const int lane = tid & 31, wid = tid >> 5;
    const int wm = wid & 1, wn = wid >> 1;        // 2 x 4 warp grid
    const int m0 = blockIdx.y * GM_BM;
    const int n0 = blockIdx.x * GM_BN;

    float acc[4][4][4];
    #pragma unroll
    for (int i = 0; i < 4; i++)
        #pragma unroll
        for (int j = 0; j < 4; j++)
            #pragma unroll
            for (int r = 0; r < 4; r++) acc[i][j][r] = 0.0f;

    float4 aR[4];
    uint4  bhR[2], blR[2];

    const int nch = K / GM_BK;

    // prefetch tile 0
    #pragma unroll
    for (int i = 0; i < 4; i++) {
        int lin = i * 256 + tid;
        int row = lin >> 3, q = lin & 7;
        int gm = m0 + row;
        float4 v = make_float4(0.f, 0.f, 0.f, 0.f);
        if (gm < M) {
            v = *(const float4*)(A + (size_t)gm * lda + q * 4);
            if (rowScale) { float s = rowScale[gm]; v.x *= s; v.y *= s; v.z *= s; v.w *= s; }
        }
        aR[i] = v;
    }
    #pragma unroll
    for (int i = 0; i < 2; i++) {
        int lin = i * 256 + tid;
        int row = lin >> 2, q = lin & 3;
        size_t go = (size_t)(n0 + row) * K + q * 8;
        bhR[i] = *(const uint4*)(Bh + go);
        blR[i] = *(const uint4*)(Bl + go);
    }

    for (int it = 0; it < nch; it++) {
        // STS prefetched tile (split A into fp16 hi/lo)
        #pragma unroll
        for (int i = 0; i < 4; i++) {
            int lin = i * 256 + tid;
            int row = lin >> 3, q = lin & 7;
            float4 v = aR[i];
            __half h0, l0, h1, l1, h2, l2, h3, l3;
            split_f16(v.x, h0, l0); split_f16(v.y, h1, l1);
            split_f16(v.z, h2, l2); split_f16(v.w, h3, l3);
            uint2 hp = make_uint2(((uint32_t)__half_as_ushort(h1) << 16) | __half_as_ushort(h0),
                                  ((uint32_t)__half_as_ushort(h3) << 16) | __half_as_ushort(h2));
            uint2 lp = make_uint2(((uint32_t)__half_as_ushort(l1) << 16) | __half_as_ushort(l0),
                                  ((uint32_t)__half_as_ushort(l3) << 16) | __half_as_ushort(l2));
            uint32_t off = (uint32_t)(row * 80 + q * 8);
            *(uint2*)(sm + SM_AH + off) = hp;
            *(uint2*)(sm + SM_AL + off) = lp;
        }
        #pragma unroll
        for (int i = 0; i < 2; i++) {
            int lin = i * 256 + tid;
            int row = lin >> 2, q = lin & 3;
            uint32_t off = (uint32_t)(row * 144 + q * 16);
            *(uint4*)(sm + SM_BH + off) = bhR[i];
            *(uint4*)(sm + SM_BL + off) = blR[i];
        }
        __syncthreads();

        // prefetch next tile
        if (it + 1 < nch) {
            int k0 = (it + 1) * GM_BK;
            #pragma unroll
            for (int i = 0; i < 4; i++) {
                int lin = i * 256 + tid;
                int row = lin >> 3, q = lin & 7;
                int gm = m0 + row;
                float4 v = make_float4(0.f, 0.f, 0.f, 0.f);
                if (gm < M) {
                    v = *(const float4*)(A + (size_t)gm * lda + k0 + q * 4);
                    if (rowScale) { float s = rowScale[gm]; v.x *= s; v.y *= s; v.z *= s; v.w *= s; }
                }
                aR[i] = v;
            }
            #pragma unroll
            for (int i = 0; i < 2; i++) {
                int lin = i * 256 + tid;
                int row = lin >> 2, q = lin & 3;
                size_t go = (size_t)(n0 + row) * K + k0 + q * 8;
                bhR[i] = *(const uint4*)(Bh + go);
                blR[i] = *(const uint4*)(Bl + go);
            }
        }

        // compute: 2 k-steps of 16
        #pragma unroll
        for (int kk = 0; kk < 2; kk++) {
            uint32_t ah[4][4], al[4][4], bh[4][2], bl[4][2];
            #pragma unroll
            for (int mt = 0; mt < 4; mt++) {
                int row = wm * 64 + mt * 16 + (lane & 15);
                uint32_t off = (uint32_t)(row * 80 + kk * 32 + ((lane >> 4) << 4));
                ldsm_x4(ah[mt], sb + SM_AH + off);
                ldsm_x4(al[mt], sb + SM_AL + off);
            }
            #pragma unroll
            for (int nt = 0; nt < 4; nt++) {
                int row = wn * 32 + nt * 8 + (lane & 7);
                uint32_t off = (uint32_t)(row * 144 + kk * 32 + (((lane >> 3) & 1) << 4));
                ldsm_x2(bh[nt], sb + SM_BH + off);
                ldsm_x2(bl[nt], sb + SM_BL + off);
            }
            #pragma unroll
            for (int mt = 0; mt < 4; mt++)
                #pragma unroll
                for (int nt = 0; nt < 4; nt++) {
                    mma_f16(acc[mt][nt], ah[mt], bh[nt]);
                    mma_f16(acc[mt][nt], ah[mt], bl[nt]);
                    mma_f16(acc[mt][nt], al[mt], bh[nt]);
                }
        }
        __syncthreads();
    }

    // epilogue
    #pragma unroll
    for (int mt = 0; mt < 4; mt++) {
        int r0 = m0 + wm * 64 + mt * 16 + (lane >> 2);
        int r1 = r0 + 8;
        float g0 = 1.0f, g1 = 1.0f;
        if (bias && rowScale) {
            g0 = (r0 < M && rowScale[r0] > 0.0f) ? 1.0f : 0.0f;
            g1 = (r1 < M && rowScale[r1] > 0.0f) ? 1.0f : 0.0f;
        }
        #pragma unroll
        for (int nt = 0; nt < 4; nt++) {
            int c0 = n0 + wn * 32 + nt * 8 + (lane & 3) * 2;
            float* d = acc[mt][nt];
            if (r0 < M) {
                float* crow = C + (size_t)r0 * ldc;
                if (c0 < Nc)     crow[c0]     = bias ? fmaf(g0, bias[c0], d[0])     : d[0];
                if (c0 + 1 < Nc) crow[c0 + 1] = bias ? fmaf(g0, bias[c0 + 1], d[1]) : d[1];
            }
            if (r1 < M) {
                float* crow = C + (size_t)r1 * ldc;
                if (c0 < Nc)     crow[c0]     = bias ? fmaf(g1, bias[c0], d[2])     : d[2];
                if (c0 + 1 < Nc) crow[c0 + 1] = bias ? fmaf(g1, bias[c0 + 1], d[3]) : d[3];
            }
        }
    }
}

// ---------------------------------------------------------------------------
// CSR edge aggregation: warp per node, no atomics, no memset.
// agg[n] = sum_{e in csr[n]} relu(C[n] + B[src_e] + b1)
// ---------------------------------------------------------------------------
__global__ __launch_bounds__(256)
void k_edge_agg_csr(const float* __restrict__ bc, const float* __restrict__ b1,
                    const int* __restrict__ csr, const int* __restrict__ estart,
                    float* __restrict__ agg, int N, int H) {
    int warp = (blockIdx.x * blockDim.x + threadIdx.x) >> 5;
    int lane = threadIdx.x & 31;
    if (warp >= N) return;
    int H4 = H >> 2;
    int nIt = (H4 + 31) >> 5;           // <= 9
    const float4* Crow = (const float4*)(bc + (size_t)warp * 2 * H);
    const float4* b14  = (const float4*)b1;

    float4 base[9], acc[9];
    #pragma unroll
    for (int j = 0; j < 9; j++) {
        acc[j] = make_float4(0.f, 0.f, 0.f, 0.f);
        if (j < nIt) {
            int h = lane + j * 32;
            if (h < H4) {
                float4 c = Crow[h], bb = b14[h];
                base[j] = make_float4(c.x + bb.x, c.y + bb.y, c.z + bb.z, c.w + bb.w);
            }
        }
    }
    int e0 = estart[warp], e1 = estart[warp + 1];
    for (int e = e0; e < e1; e++) {
        int src = csr[e];
        const float4* Brow = (const float4*)(bc + (size_t)src * 2 * H + H);
        #pragma unroll
        for (int j = 0; j < 9; j++) {
            if (j < nIt) {
                int h = lane + j * 32;
                if (h < H4) {
                    float4 b = Brow[h];
                    float v0 = base[j].x + b.x, v1 = base[j].y + b.y;
                    float v2 = base[j].z + b.z, v3 = base[j].w + b.w;
                    acc[j].x += fmaxf(v0, 0.f);
                    acc[j].y += fmaxf(v1, 0.f);
                    acc[j].z += fmaxf(v2, 0.f);
                    acc[j].w += fmaxf(v3, 0.f);
                }
            }
        }
    }
    float4* out = (float4*)(agg + (size_t)warp * H);
    #pragma unroll
    for (int j = 0; j < 9; j++) {
        if (j < nIt) {
            int h = lane + j * 32;
            if (h < H4) out[h] = acc[j];
        }
    }
}

// ---------------------------------------------------------------------------
// BatchNorm
// ---------------------------------------------------------------------------
__global__ void k_bn_stats(const float* __restrict__ t, int N, int O, double* __restrict__ sums) {
    int c = blockIdx.x * 32 + threadIdx.x;
    float s = 0.0f, s2 = 0.0f;
    if (c < O) {
        for (int r = blockIdx.y * blockDim.y + threadIdx.y; r < N; r += gridDim.y * blockDim.y) {
            float v = t[(size_t)r * O + c];
            s += v;
            s2 = fmaf(v, v, s2);
        }
    }
    __shared__ float sh[8][33], sh2[8][33];
    sh[threadIdx.y][threadIdx.x] = s;
    sh2[threadIdx.y][threadIdx.x] = s2;
    __syncthreads();
    if (threadIdx.y == 0 && c < O) {
        for (int y = 1; y < 8; y++) { s += sh[y][threadIdx.x]; s2 += sh2[y][threadIdx.x]; }
        atomicAdd(&sums[c], (double)s);
        atomicAdd(&sums[O + c], (double)s2);
    }
}
__global__ void k_bn_finalize(const double* __restrict__ sums,
                              const float* __restrict__ gamma, const float* __restrict__ beta,
                              float* __restrict__ scale, float* __restrict__ shift,
                              int N, int O) {
    int c = blockIdx.x * blockDim.x + threadIdx.x;
    if (c >= O) return;
    double mean = sums[c] / (double)N;
    double var = sums[O + c] / (double)N - mean * mean;
    float sc = gamma[c] * rsqrtf((float)var + 1e-5f);
    scale[c] = sc;
    shift[c] = beta[c] - (float)mean * sc;
}

// ---------------------------------------------------------------------------
// distribute_features: scatter (+ fused bn+relu) then gather (padded rows out)
// ---------------------------------------------------------------------------
__global__ void k_scatter(const float* __restrict__ feat, const int* __restrict__ faces,
                          float* __restrict__ vsum,
                          const float* __restrict__ scale, const float* __restrict__ shift,
                          int N, int O, int Oc, int bnrelu) {
    int idx = blockIdx.x * blockDim.x + threadIdx.x;
    int total = N * 3 * Oc;
    if (idx >= total) return;
    int r = idx / Oc, c = idx % Oc;
    int n = r / 3, k = r % 3;
    int col = k * Oc + c;
    float val = feat[(size_t)n * O + col];
    if (bnrelu) val = fmaxf(fmaf(val, scale[col], shift[col]), 0.0f);
    atomicAdd(&vsum[(size_t)faces[r] * Oc + c], val);
}
__global__ void k_gather(const float* __restrict__ vsum, const int* __restrict__ faces,
                         const float* __restrict__ vinv, float* __restrict__ out,
                         int N, int O, int Oc, int FP) {
    int idx = blockIdx.x * blockDim.x + threadIdx.x;
    if (idx >= N * FP) return;
    int n = idx / FP, col = idx % FP;
    float val = 0.0f;
    if (col < O) {
        int k = col / Oc, c = col % Oc;
        int v = faces[n * 3 + k];
        val = vsum[(size_t)v * Oc + c] * vinv[v];
    }
    out[idx] = val;
}

// ---------------------------------------------------------------------------
// Launcher
// ---------------------------------------------------------------------------
static inline int cdiv(int a, int b) { return (a + b - 1) / b; }

extern "C" void kernel_launch(void* const* d_in, const int* in_sizes, int n_in,
                              void* d_out, int out_size) {
    const float* x     = (const float*)d_in[0];
    const int*   ei    = (const int*)d_in[1];
    const int*   faces = (const int*)d_in[2];

    int N = in_sizes[0] / 16;
    int E = in_sizes[1] / 2;
    int base = (n_in >= 32 && in_sizes[3] == 1) ? 4 : 3;

    // REQUIRED: GM_SMEM (56 KB) exceeds the 48 KB default dynamic-smem limit.
    // (R10's capture failure was this missing call.)
    cudaFuncSetAttribute(k_gemm_mma, cudaFuncAttributeMaxDynamicSharedMemorySize, GM_SMEM);

    float *p_feat, *p_bc, *p_agg, *p_out2, *p_vsum, *p_scale, *p_shift, *p_invdeg, *p_vinv;
    double* p_stats;
    int *p_deg, *p_vcnt, *p_estart, *p_cursor, *p_csr, *p_csum;
    __half *p_w1h, *p_w1l, *p_w2h, *p_w2l;
    cudaGetSymbolAddress((void**)&p_feat,  g_feat);
    cudaGetSymbolAddress((void**)&p_bc,    g_bc);
    cudaGetSymbolAddress((void**)&p_agg,   g_agg);
    cudaGetSymbolAddress((void**)&p_out2,  g_out2);
    cudaGetSymbolAddress((void**)&p_vsum,  g_vsum);
    cudaGetSymbolAddress((void**)&p_scale, g_scale);
    cudaGetSymbolAddress((void**)&p_shift, g_shift);
    cudaGetSymbolAddress((void**)&p_invdeg, g_invdeg);
    cudaGetSymbolAddress((void**)&p_vinv,  g_vinv);
    cudaGetSymbolAddress((void**)&p_stats, g_stats);
    cudaGetSymbolAddress((void**)&p_deg,   g_deg);
    cudaGetSymbolAddress((void**)&p_vcnt,  g_vcnt);
    cudaGetSymbolAddress((void**)&p_estart, g_estart);
    cudaGetSymbolAddress((void**)&p_cursor, g_cursor);
    cudaGetSymbolAddress((void**)&p_csr,   g_csr);
    cudaGetSymbolAddress((void**)&p_csum,  g_csum);
    cudaGetSymbolAddress((void**)&p_w1h,   g_w1h);
    cudaGetSymbolAddress((void**)&p_w1l,   g_w1l);
    cudaGetSymbolAddress((void**)&p_w2h,   g_w2h);
    cudaGetSymbolAddress((void**)&p_w2l,   g_w2l);

    const int Fin[5] = {196, 96, 192, 384, 384};
    const int FP [5] = {256, 128, 192, 384, 384};   // padded K for GEMM1
    const int Hh [5] = {192, 384, 768, 768, 1152};
    const int Oo [5] = {96, 192, 384, 384, 576};
    const int OP [5] = {128, 256, 384, 384, 640};   // padded N (mult of 128) for GEMM2

    int nchunks = cdiv(N, 1024);

    // --- launch order: GEMM at launch indices 4 AND 5 (ncu -s 5 -c 1) ---
    cudaMemsetAsync(p_deg, 0, (size_t)N * sizeof(int), 0);                         // 0
    k_deg<<<cdiv(E, 256), 256>>>(ei, p_deg, E);                                    // 1
    {
        const float* w1 = (const float*)d_in[base + 0];
        k_prep_w1<<<cdiv(2 * Hh[0] * FP[0], 256), 256>>>(w1, p_w1h, p_w1l,
                                                         Fin[0], Hh[0], FP[0]);    // 2
    }
    k_embed<<<cdiv(N * 256, 256), 256>>>(x, p_feat, N);                            // 3
    {
        dim3 grid(2 * Hh[0] / GM_BN, cdiv(N, GM_BM));
        k_gemm_mma<<<grid, 256, GM_SMEM>>>(p_feat, p_w1h, p_w1l, p_bc,             // 4 (real)
                                           N, FP[0], 2 * Hh[0], FP[0], 2 * Hh[0],
                                           (const float*)nullptr, (const float*)nullptr);
        k_gemm_mma<<<grid, 256, GM_SMEM>>>(p_feat, p_w1h, p_w1l, p_bc,             // 5 (dup for ncu)
                                           N, FP[0], 2 * Hh[0], FP[0], 2 * Hh[0],
                                           (const float*)nullptr, (const float*)nullptr);
    }
    // CSR build + misc
    k_invdeg<<<cdiv(N, 256), 256>>>(p_deg, p_invdeg, N);
    k_chunk_sum<<<nchunks, 256>>>(p_deg, p_csum, N);
    k_chunk_scan<<<1, 32>>>(p_csum, p_estart, nchunks, N, E);
    k_node_start<<<nchunks, 32>>>(p_deg, p_csum, p_estart, p_cursor, N);
    k_fill_csr<<<cdiv(E, 256), 256>>>(ei, p_cursor, p_csr, E);
    cudaMemsetAsync(p_vcnt, 0, (size_t)VCAP * sizeof(int), 0);
    k_vcnt<<<cdiv(3 * N, 256), 256>>>(faces, p_vcnt, 3 * N);
    k_vinv<<<cdiv(VCAP, 256), 256>>>(p_vcnt, p_vinv, VCAP);

    for (int l = 0; l < 5; l++) {
        int F = Fin[l], Fp = FP[l], H = Hh[l], O = Oo[l], Op = OP[l];
        int Oc = O / 3;
        const float* w1 = (const float*)d_in[base + 4 * l + 0];
        const float* b1 = (const float*)d_in[base + 4 * l + 1];
        const float* w2 = (const float*)d_in[base + 4 * l + 2];
        const float* b2 = (const float*)d_in[base + 4 * l + 3];

        if (l > 0) {
            k_prep_w1<<<cdiv(2 * H * Fp, 256), 256>>>(w1, p_w1h, p_w1l, F, H, Fp);
            dim3 grid(2 * H / GM_BN, cdiv(N, GM_BM));
            k_gemm_mma<<<grid, 256, GM_SMEM>>>(p_feat, p_w1h, p_w1l, p_bc,
                                               N, Fp, 2 * H, Fp, 2 * H,
                                               (const float*)nullptr, (const float*)nullptr);
        }

        // CSR edge aggregation (warp per node)
        k_edge_agg_csr<<<cdiv(N * 32, 256), 256>>>(p_bc, b1, p_csr, p_estart, p_agg, N, H);

        k_prep_w2<<<cdiv(Op * H, 256), 256>>>(w2, p_w2h, p_w2l, H, O, Op);
        {
            dim3 grid(Op / GM_BN, cdiv(N, GM_BM));
            k_gemm_mma<<<grid, 256, GM_SMEM>>>(p_agg, p_w2h, p_w2l, p_out2,
                                               N, H, O, H, O, p_invdeg, b2);
        }

        int bnrelu = (l < 4) ? 1 : 0;
        if (bnrelu) {
            const float* gamma = (const float*)d_in[base + 20 + 2 * l];
            const float* beta  = (const float*)d_in[base + 21 + 2 * l];
            cudaMemsetAsync(p_stats, 0, (size_t)2 * O * sizeof(double), 0);
            dim3 grid(cdiv(O, 32), 128);
            dim3 blk(32, 8);
            k_bn_stats<<<grid, blk>>>(p_out2, N, O, p_stats);
            k_bn_finalize<<<cdiv(O, 256), 256>>>(p_stats, gamma, beta, p_scale, p_shift, N, O);
        }

        cudaMemsetAsync(p_vsum, 0, (size_t)VCAP * Oc * sizeof(float), 0);
        k_scatter<<<cdiv(3 * N * Oc, 256), 256>>>(p_out2, faces, p_vsum, p_scale, p_shift,
                                                  N, O, Oc, bnrelu);
        if (l == 4) {
            k_gather<<<cdiv(N * O, 256), 256>>>(p_vsum, faces, p_vinv, (float*)d_out, N, O, Oc, O);
        } else {
            int FPn = FP[l + 1];
            k_gather<<<cdiv(N * FPn, 256), 256>>>(p_vsum, faces, p_vinv, p_feat, N, O, Oc, FPn);
        }
    }
}

// round 14
// speedup vs baseline: 1.1067x; 1.1067x over previous
#include <cuda_runtime.h>
#include <cuda_fp16.h>
#include <math.h>
#include <stdint.h>

// ---------------------------------------------------------------------------
// Shapes: N=100000 nodes, E=300000 edges, V=50000
// Layers: F {196,96,192,384,384} (padded {256,128,192,384,384}),
//         H {192,384,768,768,1152}, O {96,192,384,384,576} (W2 N-pad {128,256,384,384,640})
// GEMM: split-fp16 (3 MMAs per k16). A pre-split to fp16 hi/lo by producers;
// cp.async double-buffered pipeline. Edge aggregation: CSR, no atomics.
// ---------------------------------------------------------------------------
#define N_NODES 100000
#define NPAD    100224
#define MAXE    300000
#define VCAP    65536
#define MAXH    1152
#define MAXO    576
#define MAXOP   640

// A operand, fp16 hi/lo (shared between feat and agg roles — lifetimes disjoint)
__device__ __half g_ah[(size_t)NPAD * MAXH];
__device__ __half g_al[(size_t)NPAD * MAXH];
__device__ float  g_bc  [(size_t)NPAD * 2 * MAXH];
__device__ float  g_out2[(size_t)NPAD * MAXO];
__device__ float  g_vsum[(size_t)VCAP * (MAXO / 3)];
__device__ double g_stats[2 * MAXO];
__device__ float  g_scale[MAXO];
__device__ float  g_shift[MAXO];
__device__ int    g_deg[N_NODES];
__device__ float  g_invdeg[N_NODES];
__device__ int    g_vcnt[VCAP];
__device__ float  g_vinv[VCAP];
__device__ int    g_estart[N_NODES + 1];
__device__ int    g_cursor[N_NODES];
__device__ int    g_csr[MAXE];
__device__ int    g_csum[128];
// fp16 hi/lo weights: W1cat^T [2H x Fpad], W2^T [Opad x H]
__device__ __half g_w1h[(size_t)2 * MAXH * 384];
__device__ __half g_w1l[(size_t)2 * MAXH * 384];
__device__ __half g_w2h[(size_t)MAXOP * MAXH];
__device__ __half g_w2l[(size_t)MAXOP * MAXH];

// ---------------------------------------------------------------------------
// PTX helpers (baseline PTX; harness targets plain sm_103 — no tcgen05)
// ---------------------------------------------------------------------------
__device__ __forceinline__ uint32_t smem_u32(const void* p) {
    uint32_t a;
    asm("{ .reg .u64 t; cvta.to.shared.u64 t, %1; cvt.u32.u64 %0, t; }" : "=r"(a) : "l"(p));
    return a;
}
__device__ __forceinline__ void ldsm_x4(uint32_t* r, uint32_t addr) {
    asm volatile("ldmatrix.sync.aligned.m8n8.x4.shared.b16 {%0,%1,%2,%3}, [%4];"
        : "=r"(r[0]), "=r"(r[1]), "=r"(r[2]), "=r"(r[3]) : "r"(addr));
}
__device__ __forceinline__ void ldsm_x2(uint32_t* r, uint32_t addr) {
    asm volatile("ldmatrix.sync.aligned.m8n8.x2.shared.b16 {%0,%1}, [%2];"
        : "=r"(r[0]), "=r"(r[1]) : "r"(addr));
}
__device__ __forceinline__ void mma_f16(float* d, const uint32_t* a, const uint32_t* b) {
    asm volatile("mma.sync.aligned.m16n8k16.row.col.f32.f16.f16.f32 "
        "{%0,%1,%2,%3}, {%4,%5,%6,%7}, {%8,%9}, {%0,%1,%2,%3};"
        : "+f"(d[0]), "+f"(d[1]), "+f"(d[2]), "+f"(d[3])
        : "r"(a[0]), "r"(a[1]), "r"(a[2]), "r"(a[3]), "r"(b[0]), "r"(b[1]));
}
__device__ __forceinline__ void cp16(uint32_t dst, const void* src, int sz) {
    asm volatile("cp.async.cg.shared.global [%0], [%1], 16, %2;"
                 :: "r"(dst), "l"(src), "r"(sz));
}
#define CP_COMMIT() asm volatile("cp.async.commit_group;")
#define CP_WAIT(n)  asm volatile("cp.async.wait_group %0;" :: "n"(n))
__device__ __forceinline__ void split_f16(float x, __half& h, __half& l) {
    h = __float2half_rn(x);
    l = __float2half_rn(x - __half2float(h));
}

// ---------------------------------------------------------------------------
// NeRF embedding -> split fp16 hi/lo, padded stride 256
// ---------------------------------------------------------------------------
__global__ void k_embed(const float* __restrict__ x, __half* __restrict__ oh,
                        __half* __restrict__ ol, int N) {
    int idx = blockIdx.x * blockDim.x + threadIdx.x;
    if (idx >= N * 256) return;
    int n = idx / 256, j = idx % 256;
    const float* xr = x + (size_t)n * 16;
    float val = 0.0f;
    if (j < 189) {
        int g = j / 63, k = j % 63;
        if (k < 3) val = xr[g * 3 + k];
        else {
            int t = k - 3;
            int d = t / 20, fr = (t % 20) >> 1, s = t & 1;
            float ang = xr[g * 3 + d] * (float)(1 << fr);
            val = s ? cosf(ang) : sinf(ang);
        }
    } else if (j < 196) {
        val = xr[9 + (j - 189)];
    }
    __half h, l; split_f16(val, h, l);
    oh[idx] = h; ol[idx] = l;
}

// ---------------------------------------------------------------------------
// Degree / vertex counts / CSR build
// ---------------------------------------------------------------------------
__global__ void k_deg(const int* __restrict__ ei, int* __restrict__ deg, int E) {
    int e = blockIdx.x * blockDim.x + threadIdx.x;
    if (e < E) atomicAdd(&deg[ei[E + e]], 1);
}
__global__ void k_invdeg(const int* __restrict__ deg, float* __restrict__ invdeg, int N) {
    int i = blockIdx.x * blockDim.x + threadIdx.x;
    if (i < N) invdeg[i] = deg[i] > 0 ? 1.0f / (float)deg[i] : 0.0f;
}
__global__ void k_vcnt(const int* __restrict__ faces, int* __restrict__ vcnt, int T3) {
    int i = blockIdx.x * blockDim.x + threadIdx.x;
    if (i < T3) atomicAdd(&vcnt[faces[i]], 1);
}
__global__ void k_vinv(const int* __restrict__ vcnt, float* __restrict__ vinv, int V) {
    int i = blockIdx.x * blockDim.x + threadIdx.x;
    if (i < V) vinv[i] = 1.0f / (float)max(vcnt[i], 1);
}
__global__ void k_chunk_sum(const int* __restrict__ deg, int* __restrict__ csum, int N) {
    __shared__ int sh[256];
    int b = blockIdx.x;
    int s = 0;
    for (int i = threadIdx.x; i < 1024; i += 256) {
        int idx = b * 1024 + i;
        if (idx < N) s += deg[idx];
    }
    sh[threadIdx.x] = s;
    __syncthreads();
    for (int st = 128; st > 0; st >>= 1) {
        if (threadIdx.x < st) sh[threadIdx.x] += sh[threadIdx.x + st];
        __syncthreads();
    }
    if (threadIdx.x == 0) csum[b] = sh[0];
}
__global__ void k_chunk_scan(int* __restrict__ csum, int* __restrict__ estart,
                             int nchunks, int N, int E) {
    if (threadIdx.x == 0 && blockIdx.x == 0) {
        int run = 0;
        for (int i = 0; i < nchunks; i++) { int v = csum[i]; csum[i] = run; run += v; }
        estart[N] = E;
    }
}
__global__ void k_node_start(const int* __restrict__ deg, const int* __restrict__ csum,
                             int* __restrict__ estart, int* __restrict__ cursor, int N) {
    int b = blockIdx.x;
    if (threadIdx.x != 0) return;
    int run = csum[b];
    int end = min((b + 1) * 1024, N);
    for (int i = b * 1024; i < end; i++) {
        estart[i] = run;
        cursor[i] = run;
        run += deg[i];
    }
}
__global__ void k_fill_csr(const int* __restrict__ ei, int* __restrict__ cursor,
                           int* __restrict__ csr, int E) {
    int e = blockIdx.x * blockDim.x + threadIdx.x;
    if (e >= E) return;
    int dst = ei[E + e];
    int p = atomicAdd(&cursor[dst], 1);
    csr[p] = ei[e];
}

// ---------------------------------------------------------------------------
// Weight prep (fp16 hi/lo)
// ---------------------------------------------------------------------------
__global__ void k_prep_w1(const float* __restrict__ w1, __half* __restrict__ bh,
                          __half* __restrict__ bl, int F, int H, int Fpad) {
    int idx = blockIdx.x * blockDim.x + threadIdx.x;
    int total = 2 * H * Fpad;
    if (idx >= total) return;
    int h2 = idx / Fpad, f = idx % Fpad;
    float v = 0.0f;
    if (f < F) {
        if (h2 < H) v = w1[(size_t)f * H + h2] - w1[(size_t)(F + f) * H + h2];
        else        v = w1[(size_t)(F + f) * H + (h2 - H)];
    }
    __half h, l; split_f16(v, h, l);
    bh[idx] = h; bl[idx] = l;
}
__global__ void k_prep_w2(const float* __restrict__ w2, __half* __restrict__ bh,
                          __half* __restrict__ bl, int H, int O, int Opad) {
    int idx = blockIdx.x * blockDim.x + threadIdx.x;
    int total = Opad * H;
    if (idx >= total) return;
    int n = idx / H, k = idx % H;
    float v = (n < O) ? w2[(size_t)k * O + n] : 0.0f;
    __half h, l; split_f16(v, h, l);
    bh[idx] = h; bl[idx] = l;
}

// ---------------------------------------------------------------------------
// Split-fp16 GEMM, cp.async double-buffered.
// C[M,Nc] = A @ Bt^T (+ bias gated on gate[r]>0). A = Ah+Al fp16 [M,lda],
// Bt = Bh+Bl fp16 [Npad,K] K-major. K mult of 32, Npad mult of 128.
// Tile 128x128, BK=32, 256 threads (2x4 warps, warp 64x32). 3 MMAs per k16.
// ---------------------------------------------------------------------------
#define GM_BM 128
#define GM_BN 128
// per-stage smem: 4 tiles x 128 rows x 80B pitch (64B data)
#define ST_AH 0
#define ST_AL 10240
#define ST_BH 20480
#define ST_BL 30720
#define GM_STAGE 40960
#define GM_SMEM  81920

__global__ __launch_bounds__(256, 1)
void k_gemm_mma(const __half* __restrict__ Ah, const __half* __restrict__ Al,
                const __half* __restrict__ Bh, const __half* __restrict__ Bl,
                float* __restrict__ C, int M, int K, int Nc, int lda, int ldc,
                const float* __restrict__ gate, const float* __restrict__ bias)
{
    extern __shared__ char sm[];
    const uint32_t sb = smem_u32(sm);
    const int tid = threadIdx.x;
    const int lane = tid & 31, wid = tid >> 5;
    const int wm = wid & 1, wn = wid >> 1;        // 2 x 4 warp grid
    const int m0 = blockIdx.y * GM_BM;
    const int n0 = blockIdx.x * GM_BN;

    float acc[4][4][4];
    #pragma unroll
    for (int i = 0; i < 4; i++)
        #pragma unroll
        for (int j = 0; j < 4; j++)
            #pragma unroll
            for (int r = 0; r < 4; r++) acc[i][j][r] = 0.0f;

    const int nch = K >> 5;

    // stage issue: 8 cp.async per thread (Ah,Al,Bh,Bl x 2 row-halves)
    auto issue = [&](int it, int buf) {
        uint32_t base = sb + buf * GM_STAGE;
        int k0 = it << 5;
        #pragma unroll
        for (int i = 0; i < 2; i++) {
            int lin = i * 256 + tid;
            int row = lin >> 2, q = lin & 3;
            int gm = m0 + row;
            int sz = (gm < M) ? 16 : 0;
            size_t ga = (size_t)((gm < M) ? gm : 0) * lda + k0 + q * 8;
            uint32_t so = (uint32_t)(row * 80 + q * 16);
            cp16(base + ST_AH + so, Ah + ga, sz);
            cp16(base + ST_AL + so, Al + ga, sz);
            size_t gb = (size_t)(n0 + row) * K + k0 + q * 8;
            cp16(base + ST_BH + so, Bh + gb, 16);
            cp16(base + ST_BL + so, Bl + gb, 16);
        }
        CP_COMMIT();
    };

    issue(0, 0);
    for (int it = 0; it < nch; it++) {
        int buf = it & 1;
        if (it + 1 < nch) { issue(it + 1, buf ^ 1); CP_WAIT(1); }
        else              { CP_WAIT(0); }
        __syncthreads();

        uint32_t base = sb + buf * GM_STAGE;
        #pragma unroll
        for (int kk = 0; kk < 2; kk++) {
            uint32_t ah[4][4], al[4][4], bh[4][2], bl[4][2];
            #pragma unroll
            for (int mt = 0; mt < 4; mt++) {
                int row = wm * 64 + mt * 16 + (lane & 15);
                uint32_t off = (uint32_t)(row * 80 + kk * 32 + ((lane >> 4) << 4));
                ldsm_x4(ah[mt], base + ST_AH + off);
                ldsm_x4(al[mt], base + ST_AL + off);
            }
            #pragma unroll
            for (int nt = 0; nt < 4; nt++) {
                int row = wn * 32 + nt * 8 + (lane & 7);
                uint32_t off = (uint32_t)(row * 80 + kk * 32 + (((lane >> 3) & 1) << 4));
                ldsm_x2(bh[nt], base + ST_BH + off);
                ldsm_x2(bl[nt], base + ST_BL + off);
            }
            #pragma unroll
            for (int mt = 0; mt < 4; mt++)
                #pragma unroll
                for (int nt = 0; nt < 4; nt++) {
                    mma_f16(acc[mt][nt], ah[mt], bh[nt]);
                    mma_f16(acc[mt][nt], ah[mt], bl[nt]);
                    mma_f16(acc[mt][nt], al[mt], bh[nt]);
                }
        }
        __syncthreads();
    }

    // epilogue (gate is gating-only; A scaling already folded in)
    #pragma unroll
    for (int mt = 0; mt < 4; mt++) {
        int r0 = m0 + wm * 64 + mt * 16 + (lane >> 2);
        int r1 = r0 + 8;
        float g0 = 1.0f, g1 = 1.0f;
        if (bias && gate) {
            g0 = (r0 < M && gate[r0] > 0.0f) ? 1.0f : 0.0f;
            g1 = (r1 < M && gate[r1] > 0.0f) ? 1.0f : 0.0f;
        }
        #pragma unroll
        for (int nt = 0; nt < 4; nt++) {
            int c0 = n0 + wn * 32 + nt * 8 + (lane & 3) * 2;
            float* d = acc[mt][nt];
            if (r0 < M) {
                float* crow = C + (size_t)r0 * ldc;
                if (c0 < Nc)     crow[c0]     = bias ? fmaf(g0, bias[c0], d[0])     : d[0];
                if (c0 + 1 < Nc) crow[c0 + 1] = bias ? fmaf(g0, bias[c0 + 1], d[1]) : d[1];
            }
            if (r1 < M) {
                float* crow = C + (size_t)r1 * ldc;
                if (c0 < Nc)     crow[c0]     = bias ? fmaf(g1, bias[c0], d[2])     : d[2];
                if (c0 + 1 < Nc) crow[c0 + 1] = bias ? fmaf(g1, bias[c0 + 1], d[3]) : d[3];
            }
        }
    }
}

// ---------------------------------------------------------------------------
// CSR edge aggregation: warp per node, no atomics. Output = invdeg-scaled
// split fp16 hi/lo (GEMM2's A operand, pre-scaled).
// ---------------------------------------------------------------------------
__global__ __launch_bounds__(256)
void k_edge_agg_csr(const float* __restrict__ bc, const float* __restrict__ b1,
                    const int* __restrict__ csr, const int* __restrict__ estart,
                    const float* __restrict__ invdeg,
                    __half* __restrict__ oh, __half* __restrict__ ol, int N, int H) {
    int warp = (blockIdx.x * blockDim.x + threadIdx.x) >> 5;
    int lane = threadIdx.x & 31;
    if (warp >= N) return;
    int H4 = H >> 2;
    int nIt = (H4 + 31) >> 5;           // <= 9
    const float4* Crow = (const float4*)(bc + (size_t)warp * 2 * H);
    const float4* b14  = (const float4*)b1;

    float4 base[9], acc[9];
    #pragma unroll
    for (int j = 0; j < 9; j++) {
        acc[j] = make_float4(0.f, 0.f, 0.f, 0.f);
        if (j < nIt) {
            int h = lane + j * 32;
            if (h < H4) {
                float4 c = Crow[h], bb = b14[h];
                base[j] = make_float4(c.x + bb.x, c.y + bb.y, c.z + bb.z, c.w + bb.w);
            }
        }
    }
    int e0 = estart[warp], e1 = estart[warp + 1];
    for (int e = e0; e < e1; e++) {
        int src = csr[e];
        const float4* Brow = (const float4*)(bc + (size_t)src * 2 * H + H);
        #pragma unroll
        for (int j = 0; j < 9; j++) {
            if (j < nIt) {
                int h = lane + j * 32;
                if (h < H4) {
                    float4 b = Brow[h];
                    acc[j].x += fmaxf(base[j].x + b.x, 0.f);
                    acc[j].y += fmaxf(base[j].y + b.y, 0.f);
                    acc[j].z += fmaxf(base[j].z + b.z, 0.f);
                    acc[j].w += fmaxf(base[j].w + b.w, 0.f);
                }
            }
        }
    }
    float inv = invdeg[warp];
    #pragma unroll
    for (int j = 0; j < 9; j++) {
        if (j < nIt) {
            int h = lane + j * 32;
            if (h < H4) {
                float v0 = acc[j].x * inv, v1 = acc[j].y * inv;
                float v2 = acc[j].z * inv, v3 = acc[j].w * inv;
                __half h0, l0, h1, l1, h2, l2, h3, l3;
                split_f16(v0, h0, l0); split_f16(v1, h1, l1);
                split_f16(v2, h2, l2); split_f16(v3, h3, l3);
                uint2 hp = make_uint2(((uint32_t)__half_as_ushort(h1) << 16) | __half_as_ushort(h0),
                                      ((uint32_t)__half_as_ushort(h3) << 16) | __half_as_ushort(h2));
                uint2 lp = make_uint2(((uint32_t)__half_as_ushort(l1) << 16) | __half_as_ushort(l0),
                                      ((uint32_t)__half_as_ushort(l3) << 16) | __half_as_ushort(l2));
                *(uint2*)(oh + (size_t)warp * H + h * 4) = hp;
                *(uint2*)(ol + (size_t)warp * H + h * 4) = lp;
            }
        }
    }
}

// ---------------------------------------------------------------------------
// BatchNorm
// ---------------------------------------------------------------------------
__global__ void k_bn_stats(const float* __restrict__ t, int N, int O, double* __restrict__ sums) {
    int c = blockIdx.x * 32 + threadIdx.x;
    float s = 0.0f, s2 = 0.0f;
    if (c < O) {
        for (int r = blockIdx.y * blockDim.y + threadIdx.y; r < N; r += gridDim.y * blockDim.y) {
            float v = t[(size_t)r * O + c];
            s += v;
            s2 = fmaf(v, v, s2);
        }
    }
    __shared__ float sh[8][33], sh2[8][33];
    sh[threadIdx.y][threadIdx.x] = s;
    sh2[threadIdx.y][threadIdx.x] = s2;
    __syncthreads();
    if (threadIdx.y == 0 && c < O) {
        for (int y = 1; y < 8; y++) { s += sh[y][threadIdx.x]; s2 += sh2[y][threadIdx.x]; }
        atomicAdd(&sums[c], (double)s);
        atomicAdd(&sums[O + c], (double)s2);
    }
}
__global__ void k_bn_finalize(const double* __restrict__ sums,
                              const float* __restrict__ gamma, const float* __restrict__ beta,
                              float* __restrict__ scale, float* __restrict__ shift,
                              int N, int O) {
    int c = blockIdx.x * blockDim.x + threadIdx.x;
    if (c >= O) return;
    double mean = sums[c] / (double)N;
    double var = sums[O + c] / (double)N - mean * mean;
    float sc = gamma[c] * rsqrtf((float)var + 1e-5f);
    scale[c] = sc;
    shift[c] = beta[c] - (float)mean * sc;
}

// ---------------------------------------------------------------------------
// distribute_features: scatter (+ fused bn+relu) then gather.
// k_gather_split writes the next layer's split-fp16 A; k_gather writes fp32 d_out.
// ---------------------------------------------------------------------------
__global__ void k_scatter(const float* __restrict__ feat, const int* __restrict__ faces,
                          float* __restrict__ vsum,
                          const float* __restrict__ scale, const float* __restrict__ shift,
                          int N, int O, int Oc, int bnrelu) {
    int idx = blockIdx.x * blockDim.x + threadIdx.x;
    int total = N * 3 * Oc;
    if (idx >= total) return;
    int r = idx / Oc, c = idx % Oc;
    int n = r / 3, k = r % 3;
    int col = k * Oc + c;
    float val = feat[(size_t)n * O + col];
    if (bnrelu) val = fmaxf(fmaf(val, scale[col], shift[col]), 0.0f);
    atomicAdd(&vsum[(size_t)faces[r] * Oc + c], val);
}
__global__ void k_gather_split(const float* __restrict__ vsum, const int* __restrict__ faces,
                               const float* __restrict__ vinv,
                               __half* __restrict__ oh, __half* __restrict__ ol,
                               int N, int O, int Oc, int FP) {
    int idx = blockIdx.x * blockDim.x + threadIdx.x;
    if (idx >= N * FP) return;
    int n = idx / FP, col = idx % FP;
    float val = 0.0f;
    if (col < O) {
        int k = col / Oc, c = col % Oc;
        int v = faces[n * 3 + k];
        val = vsum[(size_t)v * Oc + c] * vinv[v];
    }
    __half h, l; split_f16(val, h, l);
    oh[idx] = h; ol[idx] = l;
}
__global__ void k_gather(const float* __restrict__ vsum, const int* __restrict__ faces,
                         const float* __restrict__ vinv, float* __restrict__ out,
                         int N, int O, int Oc) {
    int idx = blockIdx.x * blockDim.x + threadIdx.x;
    if (idx >= N * O) return;
    int n = idx / O, col = idx % O;
    int k = col / Oc, c = col % Oc;
    int v = faces[n * 3 + k];
    out[idx] = vsum[(size_t)v * Oc + c] * vinv[v];
}

// ---------------------------------------------------------------------------
// Launcher
// ---------------------------------------------------------------------------
static inline int cdiv(int a, int b) { return (a + b - 1) / b; }

extern "C" void kernel_launch(void* const* d_in, const int* in_sizes, int n_in,
                              void* d_out, int out_size) {
    const float* x     = (const float*)d_in[0];
    const int*   ei    = (const int*)d_in[1];
    const int*   faces = (const int*)d_in[2];

    int N = in_sizes[0] / 16;
    int E = in_sizes[1] / 2;
    int base = (n_in >= 32 && in_sizes[3] == 1) ? 4 : 3;

    // GM_SMEM (80 KB) exceeds the 48 KB default dynamic-smem limit.
    cudaFuncSetAttribute(k_gemm_mma, cudaFuncAttributeMaxDynamicSharedMemorySize, GM_SMEM);

    float *p_bc, *p_out2, *p_vsum, *p_scale, *p_shift, *p_invdeg, *p_vinv;
    double* p_stats;
    int *p_deg, *p_vcnt, *p_estart, *p_cursor, *p_csr, *p_csum;
    __half *p_ah, *p_al, *p_w1h, *p_w1l, *p_w2h, *p_w2l;
    cudaGetSymbolAddress((void**)&p_ah,    g_ah);
    cudaGetSymbolAddress((void**)&p_al,    g_al);
    cudaGetSymbolAddress((void**)&p_bc,    g_bc);
    cudaGetSymbolAddress((void**)&p_out2,  g_out2);
    cudaGetSymbolAddress((void**)&p_vsum,  g_vsum);
    cudaGetSymbolAddress((void**)&p_scale, g_scale);
    cudaGetSymbolAddress((void**)&p_shift, g_shift);
    cudaGetSymbolAddress((void**)&p_invdeg, g_invdeg);
    cudaGetSymbolAddress((void**)&p_vinv,  g_vinv);
    cudaGetSymbolAddress((void**)&p_stats, g_stats);
    cudaGetSymbolAddress((void**)&p_deg,   g_deg);
    cudaGetSymbolAddress((void**)&p_vcnt,  g_vcnt);
    cudaGetSymbolAddress((void**)&p_estart, g_estart);
    cudaGetSymbolAddress((void**)&p_cursor, g_cursor);
    cudaGetSymbolAddress((void**)&p_csr,   g_csr);
    cudaGetSymbolAddress((void**)&p_csum,  g_csum);
    cudaGetSymbolAddress((void**)&p_w1h,   g_w1h);
    cudaGetSymbolAddress((void**)&p_w1l,   g_w1l);
    cudaGetSymbolAddress((void**)&p_w2h,   g_w2h);
    cudaGetSymbolAddress((void**)&p_w2l,   g_w2l);

    const int Fin[5] = {196, 96, 192, 384, 384};
    const int FP [5] = {256, 128, 192, 384, 384};   // padded K for GEMM1
    const int Hh [5] = {192, 384, 768, 768, 1152};
    const int Oo [5] = {96, 192, 384, 384, 576};
    const int OP [5] = {128, 256, 384, 384, 640};   // padded N (mult of 128) for GEMM2

    int nchunks = cdiv(N, 1024);

    // --- launch order: GEMM at launch indices 4 AND 5 (ncu -s 5 -c 1) ---
    cudaMemsetAsync(p_deg, 0, (size_t)N * sizeof(int), 0);                         // 0
    k_deg<<<cdiv(E, 256), 256>>>(ei, p_deg, E);                                    // 1
    {
        const float* w1 = (const float*)d_in[base + 0];
        k_prep_w1<<<cdiv(2 * Hh[0] * FP[0], 256), 256>>>(w1, p_w1h, p_w1l,
                                                         Fin[0], Hh[0], FP[0]);    // 2
    }
    k_embed<<<cdiv(N * 256, 256), 256>>>(x, p_ah, p_al, N);                        // 3
    {
        dim3 grid(2 * Hh[0] / GM_BN, cdiv(N, GM_BM));
        k_gemm_mma<<<grid, 256, GM_SMEM>>>(p_ah, p_al, p_w1h, p_w1l, p_bc,         // 4 (real)
                                           N, FP[0], 2 * Hh[0], FP[0], 2 * Hh[0],
                                           (const float*)nullptr, (const float*)nullptr);
        k_gemm_mma<<<grid, 256, GM_SMEM>>>(p_ah, p_al, p_w1h, p_w1l, p_bc,         // 5 (dup for ncu)
                                           N, FP[0], 2 * Hh[0], FP[0], 2 * Hh[0],
                                           (const float*)nullptr, (const float*)nullptr);
    }
    // CSR build + misc
    k_invdeg<<<cdiv(N, 256), 256>>>(p_deg, p_invdeg, N);
    k_chunk_sum<<<nchunks, 256>>>(p_deg, p_csum, N);
    k_chunk_scan<<<1, 32>>>(p_csum, p_estart, nchunks, N, E);
    k_node_start<<<nchunks, 32>>>(p_deg, p_csum, p_estart, p_cursor, N);
    k_fill_csr<<<cdiv(E, 256), 256>>>(ei, p_cursor, p_csr, E);
    cudaMemsetAsync(p_vcnt, 0, (size_t)VCAP * sizeof(int), 0);
    k_vcnt<<<cdiv(3 * N, 256), 256>>>(faces, p_vcnt, 3 * N);
    k_vinv<<<cdiv(VCAP, 256), 256>>>(p_vcnt, p_vinv, VCAP);

    for (int l = 0; l < 5; l++) {
        int F = Fin[l], Fp = FP[l], H = Hh[l], O = Oo[l], Op = OP[l];
        int Oc = O / 3;
        const float* w1 = (const float*)d_in[base + 4 * l + 0];
        const float* b1 = (const float*)d_in[base + 4 * l + 1];
        const float* w2 = (const float*)d_in[base + 4 * l + 2];
        const float* b2 = (const float*)d_in[base + 4 * l + 3];

        if (l > 0) {
            k_prep_w1<<<cdiv(2 * H * Fp, 256), 256>>>(w1, p_w1h, p_w1l, F, H, Fp);
            dim3 grid(2 * H / GM_BN, cdiv(N, GM_BM));
            k_gemm_mma<<<grid, 256, GM_SMEM>>>(p_ah, p_al, p_w1h, p_w1l, p_bc,
                                               N, Fp, 2 * H, Fp, 2 * H,
                                               (const float*)nullptr, (const float*)nullptr);
        }

        // CSR edge aggregation -> split fp16 A for GEMM2 (invdeg folded in)
        k_edge_agg_csr<<<cdiv(N * 32, 256), 256>>>(p_bc, b1, p_csr, p_estart,
                                                   p_invdeg, p_ah, p_al, N, H);

        k_prep_w2<<<cdiv(Op * H, 256), 256>>>(w2, p_w2h, p_w2l, H, O, Op);
        {
            dim3 grid(Op / GM_BN, cdiv(N, GM_BM));
            k_gemm_mma<<<grid, 256, GM_SMEM>>>(p_ah, p_al, p_w2h, p_w2l, p_out2,
                                               N, H, O, H, O, p_invdeg, b2);
        }

        int bnrelu = (l < 4) ? 1 : 0;
        if (bnrelu) {
            const float* gamma = (const float*)d_in[base + 20 + 2 * l];
            const float* beta  = (const float*)d_in[base + 21 + 2 * l];
            cudaMemsetAsync(p_stats, 0, (size_t)2 * O * sizeof(double), 0);
            dim3 grid(cdiv(O, 32), 128);
            dim3 blk(32, 8);
            k_bn_stats<<<grid, blk>>>(p_out2, N, O, p_stats);
            k_bn_finalize<<<cdiv(O, 256), 256>>>(p_stats, gamma, beta, p_scale, p_shift, N, O);
        }

        cudaMemsetAsync(p_vsum, 0, (size_t)VCAP * Oc * sizeof(float), 0);
        k_scatter<<<cdiv(3 * N * Oc, 256), 256>>>(p_out2, faces, p_vsum, p_scale, p_shift,
                                                  N, O, Oc, bnrelu);
        if (l == 4) {
            k_gather<<<cdiv(N * O, 256), 256>>>(p_vsum, faces, p_vinv, (float*)d_out, N, O, Oc);
        } else {
            int FPn = FP[l + 1];
            k_gather_split<<<cdiv(N * FPn, 256), 256>>>(p_vsum, faces, p_vinv,
                                                        p_ah, p_al, N, O, Oc, FPn);
        }
    }
}